// round 12
// baseline (speedup 1.0000x reference)
#include <cuda_runtime.h>
#include <cuda_fp16.h>

#define NN 100000
#define EE 1600000
#define DIN 128
#define HIDD 64
#define GG 256
#define NLAYERS 3
#define BN_EPS 1e-5f
#define NB_SCAN ((NN + 255) / 256)   // 391
#define GEMM_BLOCKS 782              // ceil(NN/128)
#define AUX_BLOCKS 2048

// ---------------- device scratch (no allocs allowed) ----------------
__device__ __align__(16) int    g_cnt[NN];
__device__ __align__(16) int    g_off[NN + 1];   // block-local exclusive prefix
__device__ __align__(16) int    g_bsum[NB_SCAN];
__device__ __align__(16) int    g_boff[512];     // per-256-block absolute base
__device__ __align__(16) float  g_dinv[NN];
__device__ __align__(16) int    g_rank[EE];      // intra-dst rank (from count pass)
__device__ __align__(16) int2   g_csr[EE];       // .x = src, .y = bits(norm)
__device__ __align__(16) int    g_batch[NN];
__device__ __align__(16) __half g_h[NN * HIDD];           // fp16 (GEMM A operand)
__device__ __align__(16) unsigned char g_hw8[NN * HIDD];  // fp8 e4m3 (gather input)
__device__ __align__(16) float  g_gsum[GG * HIDD];
__device__ __align__(16) float  g_gcnt[GG];
__device__ int g_is64;
__device__ int g_scan_ct;

// ---------------- fp8 helpers ----------------
__device__ __forceinline__ unsigned short f2_to_fp8x2(float lo, float hi) {
    unsigned short r;
    asm("cvt.rn.satfinite.e4m3x2.f32 %0, %2, %1;" : "=h"(r) : "f"(lo), "f"(hi));
    return r;   // byte0 = lo, byte1 = hi
}
__device__ __forceinline__ float2 fp8x2_to_f2(unsigned short v) {
    unsigned h2;
    asm("cvt.rn.f16x2.e4m3x2 %0, %1;" : "=r"(h2) : "h"(v));
    return __half22float2(*(__half2*)&h2);
}
__device__ __forceinline__ float4 fp8x4_to_f4(unsigned v) {
    float2 a = fp8x2_to_f2((unsigned short)(v & 0xFFFFu));
    float2 b = fp8x2_to_f2((unsigned short)(v >> 16));
    return make_float4(a.x, a.y, b.x, b.y);
}

// ---------------- init (+ inline dtype detection) ----------------
__global__ void k_init(const int* __restrict__ ei) {
    int i = blockIdx.x * blockDim.x + threadIdx.x;
    if (i < NN) g_cnt[i] = 0;
    if (i < GG * HIDD) g_gsum[i] = 0.f;
    if (i < GG) g_gcnt[i] = 0.f;
    if (i == 0) {
        g_scan_ct = 0;
        int nz = 0;
        for (int j = 0; j < 32; j++) nz |= ei[2 * j + 1];
        g_is64 = (nz == 0) ? 1 : 0;
    }
}

// ---------------- HMMA m16n8k16 (fp16 x fp16 -> fp32) ----------------
__device__ __forceinline__ void hmma(float* c, unsigned a0, unsigned a1,
                                     unsigned a2, unsigned a3,
                                     unsigned b0, unsigned b1) {
    asm("mma.sync.aligned.m16n8k16.row.col.f32.f16.f16.f32 "
        "{%0,%1,%2,%3}, {%4,%5,%6,%7}, {%8,%9}, {%0,%1,%2,%3};"
        : "+f"(c[0]), "+f"(c[1]), "+f"(c[2]), "+f"(c[3])
        : "r"(a0), "r"(a1), "r"(a2), "r"(a3), "r"(b0), "r"(b1));
}

// ---------------- mega 1: [blocks 0..781] h0 GEMM | [rest] count+rank --------
__global__ void __launch_bounds__(256) k_mega_in(
        const float* __restrict__ x, const float* __restrict__ W,
        const float* __restrict__ bias, const int* __restrict__ ei,
        const int* __restrict__ bt, __half* __restrict__ C) {
    __shared__ __half sA[128][72];
    __shared__ __half sB[64][136];
    const int tid = threadIdx.x;

    if (blockIdx.x >= GEMM_BLOCKS) {
        const bool is64 = (g_is64 != 0);
        const int nb = gridDim.x - GEMM_BLOCKS;
        const int bb = blockIdx.x - GEMM_BLOCKS;
        const int stride = nb * 256;
        for (int i = bb * 256 + tid; i < EE; i += stride) {
            int d = is64 ? ei[2 * (EE + i)] : ei[EE + i];
            g_rank[i] = atomicAdd(&g_cnt[d], 1);
        }
        for (int i = bb * 256 + tid; i < NN; i += stride) {
            int b = is64 ? bt[2 * i] : bt[i];
            g_batch[i] = b;
            atomicAdd(&g_gcnt[b], 1.f);
        }
        return;
    }

    const int warp = tid >> 5, lane = tid & 31;
    const int g = lane >> 2, tq = lane & 3;
    const int base = blockIdx.x * 128;

    for (int t = tid; t < DIN * HIDD; t += 256) {
        int k = t >> 6, n = t & 63;
        sB[n][k] = __float2half(W[t]);
    }

    float c[8][4];
#pragma unroll
    for (int nt = 0; nt < 8; nt++)
#pragma unroll
        for (int j = 0; j < 4; j++) c[nt][j] = 0.f;

#pragma unroll
    for (int half = 0; half < 2; half++) {
        __syncthreads();
        for (int t = tid; t < 128 * 32; t += 256) {
            int row = t >> 5, p = t & 31;
            int node = base + row;
            float2 v = (node < NN)
                ? *(const float2*)&x[(long)node * DIN + half * 64 + p * 2]
                : make_float2(0.f, 0.f);
            *(__half2*)&sA[row][p * 2] = __floats2half2_rn(v.x, v.y);
        }
        __syncthreads();
#pragma unroll
        for (int ks = 0; ks < 4; ks++) {
            int k0 = ks * 16 + tq * 2;
            unsigned a0 = *(const unsigned*)&sA[warp * 16 + g][k0];
            unsigned a1 = *(const unsigned*)&sA[warp * 16 + g + 8][k0];
            unsigned a2 = *(const unsigned*)&sA[warp * 16 + g][k0 + 8];
            unsigned a3 = *(const unsigned*)&sA[warp * 16 + g + 8][k0 + 8];
#pragma unroll
            for (int nt = 0; nt < 8; nt++) {
                unsigned b0 = *(const unsigned*)&sB[nt * 8 + g][half * 64 + k0];
                unsigned b1 = *(const unsigned*)&sB[nt * 8 + g][half * 64 + k0 + 8];
                hmma(c[nt], a0, a1, a2, a3, b0, b1);
            }
        }
    }

    const int r0 = base + warp * 16 + g;
    const int r1 = r0 + 8;
#pragma unroll
    for (int nt = 0; nt < 8; nt++) {
        int c0 = nt * 8 + tq * 2;
        float bv0 = bias[c0], bv1 = bias[c0 + 1];
        if (r0 < NN)
            *(__half2*)&C[(long)r0 * HIDD + c0] =
                __floats2half2_rn(c[nt][0] + bv0, c[nt][1] + bv1);
        if (r1 < NN)
            *(__half2*)&C[(long)r1 * HIDD + c0] =
                __floats2half2_rn(c[nt][2] + bv0, c[nt][3] + bv1);
    }
}

// ---------------- merged prefix scan (block scans + last-block top scan) -----
__global__ void k_scan() {
    __shared__ int s[256];
    __shared__ int p[256];
    __shared__ bool amLast;
    int b = blockIdx.x, t = threadIdx.x, i = b * 256 + t;
    int v = (i < NN) ? g_cnt[i] : 0;
    if (i < NN) g_dinv[i] = rsqrtf((float)(v + 1));
    s[t] = v; __syncthreads();
#pragma unroll
    for (int o = 1; o < 256; o <<= 1) {
        int x = (t >= o) ? s[t - o] : 0;
        __syncthreads();
        s[t] += x;
        __syncthreads();
    }
    if (i < NN) g_off[i] = s[t] - v;
    if (t == 255) g_bsum[b] = s[255];

    __threadfence();
    if (t == 0) amLast = (atomicAdd(&g_scan_ct, 1) == gridDim.x - 1);
    __syncthreads();
    if (!amLast) return;

    int e0 = (2 * t < NB_SCAN) ? g_bsum[2 * t] : 0;
    int e1 = (2 * t + 1 < NB_SCAN) ? g_bsum[2 * t + 1] : 0;
    int pv = e0 + e1;
    p[t] = pv; __syncthreads();
#pragma unroll
    for (int o = 1; o < 256; o <<= 1) {
        int x = (t >= o) ? p[t - o] : 0;
        __syncthreads();
        p[t] += x;
        __syncthreads();
    }
    int excl = p[t] - pv;
    g_boff[2 * t] = excl;
    g_boff[2 * t + 1] = excl + e0;
    if (2 * t == (NN >> 8)) g_off[NN] = EE - excl;
    if (2 * t + 1 == (NN >> 8)) g_off[NN] = EE - (excl + e0);
}

// ---------------- mega 2: [blocks 0..AUX-1] place (no atomic) | [rest] hw0 ---
__global__ void __launch_bounds__(256) k_mega_place(
        const int* __restrict__ ei, const __half* __restrict__ A,
        const float* __restrict__ W, unsigned char* __restrict__ C8) {
    __shared__ __half sB[64][72];
    const int tid = threadIdx.x;

    if (blockIdx.x < AUX_BLOCKS) {
        const bool is64 = (g_is64 != 0);
        const int stride = AUX_BLOCKS * 256;
        for (int e = blockIdx.x * 256 + tid; e < EE; e += stride) {
            int s = is64 ? ei[2 * e] : ei[e];
            int d = is64 ? ei[2 * (EE + e)] : ei[EE + e];
            float w = g_dinv[s] * g_dinv[d];
            int pos = g_off[d] + g_boff[d >> 8] + g_rank[e];
            g_csr[pos] = make_int2(s, __float_as_int(w));
        }
        return;
    }

    const int warp = tid >> 5, lane = tid & 31;
    const int g = lane >> 2, tq = lane & 3;

    for (int t = tid; t < HIDD * HIDD; t += 256) {
        int k = t >> 6, n = t & 63;
        sB[n][k] = __float2half(W[t]);
    }
    __syncthreads();

    const int r0 = (blockIdx.x - AUX_BLOCKS) * 128 + warp * 16 + g;
    const int r1 = r0 + 8;
    const bool v0 = (r0 < NN), v1 = (r1 < NN);
    const __half* A0 = A + (long)(v0 ? r0 : 0) * HIDD;
    const __half* A1 = A + (long)(v1 ? r1 : 0) * HIDD;

    float c[8][4];
#pragma unroll
    for (int nt = 0; nt < 8; nt++)
#pragma unroll
        for (int j = 0; j < 4; j++) c[nt][j] = 0.f;

#pragma unroll
    for (int ks = 0; ks < 4; ks++) {
        int k0 = ks * 16 + tq * 2;
        unsigned a0 = *(const unsigned*)&A0[k0];
        unsigned a1 = *(const unsigned*)&A1[k0];
        unsigned a2 = *(const unsigned*)&A0[k0 + 8];
        unsigned a3 = *(const unsigned*)&A1[k0 + 8];
#pragma unroll
        for (int nt = 0; nt < 8; nt++) {
            unsigned b0 = *(const unsigned*)&sB[nt * 8 + g][k0];
            unsigned b1 = *(const unsigned*)&sB[nt * 8 + g][k0 + 8];
            hmma(c[nt], a0, a1, a2, a3, b0, b1);
        }
    }

#pragma unroll
    for (int nt = 0; nt < 8; nt++) {
        int c0 = nt * 8 + tq * 2;
        if (v0) *(unsigned short*)&C8[(long)r0 * HIDD + c0] = f2_to_fp8x2(c[nt][0], c[nt][1]);
        if (v1) *(unsigned short*)&C8[(long)r1 * HIDD + c0] = f2_to_fp8x2(c[nt][2], c[nt][3]);
    }
}

// ---------------- standalone layer GEMM: hw8 = fp8(h @ W) --------------------
__global__ void __launch_bounds__(256) k_gemm_h_mma(
        const __half* __restrict__ A, const float* __restrict__ W,
        unsigned char* __restrict__ C8) {
    __shared__ __half sB[64][72];
    const int tid = threadIdx.x;
    const int warp = tid >> 5, lane = tid & 31;
    const int g = lane >> 2, tq = lane & 3;

    for (int t = tid; t < HIDD * HIDD; t += 256) {
        int k = t >> 6, n = t & 63;
        sB[n][k] = __float2half(W[t]);
    }
    __syncthreads();

    const int r0 = blockIdx.x * 128 + warp * 16 + g;
    const int r1 = r0 + 8;
    const bool v0 = (r0 < NN), v1 = (r1 < NN);
    const __half* A0 = A + (long)(v0 ? r0 : 0) * HIDD;
    const __half* A1 = A + (long)(v1 ? r1 : 0) * HIDD;

    float c[8][4];
#pragma unroll
    for (int nt = 0; nt < 8; nt++)
#pragma unroll
        for (int j = 0; j < 4; j++) c[nt][j] = 0.f;

#pragma unroll
    for (int ks = 0; ks < 4; ks++) {
        int k0 = ks * 16 + tq * 2;
        unsigned a0 = *(const unsigned*)&A0[k0];
        unsigned a1 = *(const unsigned*)&A1[k0];
        unsigned a2 = *(const unsigned*)&A0[k0 + 8];
        unsigned a3 = *(const unsigned*)&A1[k0 + 8];
#pragma unroll
        for (int nt = 0; nt < 8; nt++) {
            unsigned b0 = *(const unsigned*)&sB[nt * 8 + g][k0];
            unsigned b1 = *(const unsigned*)&sB[nt * 8 + g][k0 + 8];
            hmma(c[nt], a0, a1, a2, a3, b0, b1);
        }
    }

#pragma unroll
    for (int nt = 0; nt < 8; nt++) {
        int c0 = nt * 8 + tq * 2;
        if (v0) *(unsigned short*)&C8[(long)r0 * HIDD + c0] = f2_to_fp8x2(c[nt][0], c[nt][1]);
        if (v1) *(unsigned short*)&C8[(long)r1 * HIDD + c0] = f2_to_fp8x2(c[nt][2], c[nt][3]);
    }
}

// ---------------- gather + epilogue (half-warp per edge stream) --------------
// Warp = 1 node. Lanes 0-15 process even-offset edges, lanes 16-31 odd.
// Lane L covers cols 4L..4L+3 (one 4B fp8x4 load per edge). Unroll 2 -> 4
// independent edge chains per warp. Halves merged by shfl at the end.
template <int POOL>
__global__ void k_gather_ep(const unsigned char* __restrict__ hw8,
                            const float* __restrict__ cb,
                            const float* __restrict__ gamma,
                            const float* __restrict__ beta,
                            const float* __restrict__ mean,
                            const float* __restrict__ var,
                            __half* __restrict__ hout) {
    int gw = (blockIdx.x * blockDim.x + threadIdx.x) >> 5;
    int lane = threadIdx.x & 31;
    if (gw >= NN) return;
    const int hl = lane >> 4;       // half 0/1
    const int L = lane & 15;
    const int c0 = L * 4;

    // hoisted epilogue constants (4 cols per lane)
    float4 gm = *(const float4*)&gamma[c0];
    float4 vr = *(const float4*)&var[c0];
    float4 bv = *(const float4*)&cb[c0];
    float4 mn = *(const float4*)&mean[c0];
    float4 be = *(const float4*)&beta[c0];

    float di = g_dinv[gw];
    float swt = di * di;
    float4 acc = make_float4(0.f, 0.f, 0.f, 0.f);
    if (hl == 0) {
        float4 sv = fp8x4_to_f4(*(const unsigned*)&hw8[(long)gw * HIDD + c0]);
        acc.x = sv.x * swt; acc.y = sv.y * swt; acc.z = sv.z * swt; acc.w = sv.w * swt;
    }

    int e = g_off[gw] + g_boff[gw >> 8] + hl;
    const int end = g_off[gw + 1] + g_boff[(gw + 1) >> 8];
    // unroll 2 (edges e, e+2 for this half)
    for (; e + 2 < end; e += 4) {
        int2 m0 = g_csr[e];
        int2 m1 = g_csr[e + 2];
        unsigned r0 = *(const unsigned*)&hw8[(long)m0.x * HIDD + c0];
        unsigned r1 = *(const unsigned*)&hw8[(long)m1.x * HIDD + c0];
        float w0 = __int_as_float(m0.y), w1 = __int_as_float(m1.y);
        float4 v0 = fp8x4_to_f4(r0);
        float4 v1 = fp8x4_to_f4(r1);
        acc.x += w0 * v0.x + w1 * v1.x;
        acc.y += w0 * v0.y + w1 * v1.y;
        acc.z += w0 * v0.z + w1 * v1.z;
        acc.w += w0 * v0.w + w1 * v1.w;
    }
    if (e < end) {
        int2 m = g_csr[e];
        float w = __int_as_float(m.y);
        float4 v = fp8x4_to_f4(*(const unsigned*)&hw8[(long)m.x * HIDD + c0]);
        acc.x += w * v.x; acc.y += w * v.y; acc.z += w * v.z; acc.w += w * v.w;
    }

    __syncwarp();
    acc.x += __shfl_down_sync(0xffffffffu, acc.x, 16);
    acc.y += __shfl_down_sync(0xffffffffu, acc.y, 16);
    acc.z += __shfl_down_sync(0xffffffffu, acc.z, 16);
    acc.w += __shfl_down_sync(0xffffffffu, acc.w, 16);
    if (hl != 0) return;

    float sc0 = gm.x * rsqrtf(vr.x + BN_EPS), sh0 = (bv.x - mn.x) * sc0 + be.x;
    float sc1 = gm.y * rsqrtf(vr.y + BN_EPS), sh1 = (bv.y - mn.y) * sc1 + be.y;
    float sc2 = gm.z * rsqrtf(vr.z + BN_EPS), sh2 = (bv.z - mn.z) * sc2 + be.z;
    float sc3 = gm.w * rsqrtf(vr.w + BN_EPS), sh3 = (bv.w - mn.w) * sc3 + be.w;
    float o0 = fmaxf(acc.x * sc0 + sh0, 0.f);
    float o1 = fmaxf(acc.y * sc1 + sh1, 0.f);
    float o2 = fmaxf(acc.z * sc2 + sh2, 0.f);
    float o3 = fmaxf(acc.w * sc3 + sh3, 0.f);
    if (POOL) {
        int b = g_batch[gw];
        atomicAdd((float4*)&g_gsum[b * HIDD + c0], make_float4(o0, o1, o2, o3));
    } else {
        __half2 q0 = __floats2half2_rn(o0, o1);
        __half2 q1 = __floats2half2_rn(o2, o3);
        __half2* p = (__half2*)&hout[(long)gw * HIDD + c0];
        p[0] = q0; p[1] = q1;
    }
}

// ---------------- MLP head ----------------
__global__ void k_mlp(const float* __restrict__ W1, const float* __restrict__ b1,
                      const float* __restrict__ W2, const float* __restrict__ b2,
                      const float* __restrict__ W3, const float* __restrict__ b3,
                      float* __restrict__ out) {
    __shared__ float v[64], a1[64], a2[32];
    int g = blockIdx.x;
    int c = threadIdx.x;
    float cnt = fmaxf(g_gcnt[g], 1.f);
    v[c] = g_gsum[g * HIDD + c] / cnt;
    __syncthreads();
    float s = b1[c];
#pragma unroll
    for (int k = 0; k < 64; k++) s += v[k] * W1[k * 64 + c];
    a1[c] = fmaxf(s, 0.f);
    __syncthreads();
    if (c < 32) {
        float s2 = b2[c];
#pragma unroll
        for (int k = 0; k < 64; k++) s2 += a1[k] * W2[k * 32 + c];
        a2[c] = fmaxf(s2, 0.f);
    }
    __syncthreads();
    if (c < 32) {
        float p = a2[c] * W3[c];
#pragma unroll
        for (int o = 16; o > 0; o >>= 1) p += __shfl_down_sync(0xffffffff, p, o);
        if (c == 0) out[g] = p + b3[0];
    }
}

// ---------------- launch ----------------
extern "C" void kernel_launch(void* const* d_in, const int* in_sizes, int n_in,
                              void* d_out, int out_size) {
    const float* x      = (const float*)d_in[0];
    const int*   ei     = (const int*)d_in[1];
    const int*   bt     = (const int*)d_in[2];
    const float* W_in   = (const float*)d_in[3];
    const float* b_in   = (const float*)d_in[4];
    const float* conv_W = (const float*)d_in[5];
    const float* conv_b = (const float*)d_in[6];
    const float* gamma  = (const float*)d_in[7];
    const float* beta   = (const float*)d_in[8];
    const float* mean   = (const float*)d_in[9];
    const float* var    = (const float*)d_in[10];
    const float* W1     = (const float*)d_in[11];
    const float* b1     = (const float*)d_in[12];
    const float* W2     = (const float*)d_in[13];
    const float* b2     = (const float*)d_in[14];
    const float* W3     = (const float*)d_in[15];
    const float* b3     = (const float*)d_in[16];
    float* out = (float*)d_out;

    __half* p_h = nullptr;
    unsigned char* p_hw8 = nullptr;
    cudaGetSymbolAddress((void**)&p_h, g_h);
    cudaGetSymbolAddress((void**)&p_hw8, g_hw8);

    const int gather_blocks = (NN * 32 + 255) / 256;

    k_init<<<(NN + 255) / 256, 256>>>(ei);
    // overlap: input GEMM + edge counting (with rank capture)
    k_mega_in<<<GEMM_BLOCKS + AUX_BLOCKS, 256>>>(x, W_in, b_in, ei, bt, p_h);
    k_scan<<<NB_SCAN, 256>>>();
    // overlap: atomic-free CSR placement + layer-0 transform (fp8 out)
    k_mega_place<<<AUX_BLOCKS + GEMM_BLOCKS, 256>>>(ei, p_h, conv_W, p_hw8);

    // layer 0 gather -> h1
    k_gather_ep<0><<<gather_blocks, 256>>>(p_hw8, conv_b, gamma, beta, mean, var, p_h);
    // layer 1
    k_gemm_h_mma<<<GEMM_BLOCKS, 256>>>(p_h, conv_W + 1L * HIDD * HIDD, p_hw8);
    k_gather_ep<0><<<gather_blocks, 256>>>(p_hw8, conv_b + HIDD, gamma + HIDD,
                                           beta + HIDD, mean + HIDD, var + HIDD, p_h);
    // layer 2
    k_gemm_h_mma<<<GEMM_BLOCKS, 256>>>(p_h, conv_W + 2L * HIDD * HIDD, p_hw8);
    k_gather_ep<1><<<gather_blocks, 256>>>(p_hw8, conv_b + 2 * HIDD, gamma + 2 * HIDD,
                                           beta + 2 * HIDD, mean + 2 * HIDD,
                                           var + 2 * HIDD, p_h);

    k_mlp<<<GG, 64>>>(W1, b1, W2, b2, W3, b3, out);
}

// round 13
// speedup vs baseline: 1.2228x; 1.2228x over previous
#include <cuda_runtime.h>
#include <cuda_fp16.h>

#define NN 100000
#define EE 1600000
#define DIN 128
#define HIDD 64
#define GG 256
#define NLAYERS 3
#define BN_EPS 1e-5f
#define NB_SCAN ((NN + 255) / 256)   // 391
#define GEMM_BLOCKS 782              // ceil(NN/128)
#define AUX_BLOCKS 2048

// ---------------- device scratch (no allocs allowed) ----------------
__device__ __align__(16) int    g_cnt[NN];
__device__ __align__(16) int    g_off[NN + 1];   // block-local exclusive prefix
__device__ __align__(16) int    g_bsum[NB_SCAN];
__device__ __align__(16) int    g_boff[512];     // per-256-block absolute base
__device__ __align__(16) float  g_dinv[NN];
__device__ __align__(16) int    g_rank[EE];      // intra-dst rank (from count pass)
__device__ __align__(16) int2   g_csr[EE];       // .x = src, .y = bits(norm)
__device__ __align__(16) int    g_batch[NN];
__device__ __align__(16) __half g_h[NN * HIDD];           // fp16 (GEMM A operand)
__device__ __align__(16) unsigned char g_hw8[NN * HIDD];  // fp8 e4m3 (gather input)
__device__ __align__(16) float  g_gsum[GG * HIDD];
__device__ __align__(16) float  g_gcnt[GG];
__device__ int g_is64;
__device__ int g_scan_ct;

// ---------------- fp8 helpers ----------------
__device__ __forceinline__ unsigned short f2_to_fp8x2(float lo, float hi) {
    unsigned short r;
    asm("cvt.rn.satfinite.e4m3x2.f32 %0, %2, %1;" : "=h"(r) : "f"(lo), "f"(hi));
    return r;   // byte0 = lo, byte1 = hi
}
__device__ __forceinline__ float2 fp8x2_to_f2(unsigned short v) {
    unsigned h2;
    asm("cvt.rn.f16x2.e4m3x2 %0, %1;" : "=r"(h2) : "h"(v));
    return __half22float2(*(__half2*)&h2);
}

// ---------------- init (+ inline dtype detection) ----------------
__global__ void k_init(const int* __restrict__ ei) {
    int i = blockIdx.x * blockDim.x + threadIdx.x;
    if (i < NN) g_cnt[i] = 0;
    if (i < GG * HIDD) g_gsum[i] = 0.f;
    if (i < GG) g_gcnt[i] = 0.f;
    if (i == 0) {
        g_scan_ct = 0;
        int nz = 0;
        for (int j = 0; j < 32; j++) nz |= ei[2 * j + 1];
        g_is64 = (nz == 0) ? 1 : 0;
    }
}

// ---------------- HMMA m16n8k16 (fp16 x fp16 -> fp32) ----------------
__device__ __forceinline__ void hmma(float* c, unsigned a0, unsigned a1,
                                     unsigned a2, unsigned a3,
                                     unsigned b0, unsigned b1) {
    asm("mma.sync.aligned.m16n8k16.row.col.f32.f16.f16.f32 "
        "{%0,%1,%2,%3}, {%4,%5,%6,%7}, {%8,%9}, {%0,%1,%2,%3};"
        : "+f"(c[0]), "+f"(c[1]), "+f"(c[2]), "+f"(c[3])
        : "r"(a0), "r"(a1), "r"(a2), "r"(a3), "r"(b0), "r"(b1));
}

// ---------------- mega 1: [blocks 0..781] h0 GEMM | [rest] count+rank --------
__global__ void __launch_bounds__(256) k_mega_in(
        const float* __restrict__ x, const float* __restrict__ W,
        const float* __restrict__ bias, const int* __restrict__ ei,
        const int* __restrict__ bt, __half* __restrict__ C) {
    __shared__ __half sA[128][72];
    __shared__ __half sB[64][136];
    const int tid = threadIdx.x;

    if (blockIdx.x >= GEMM_BLOCKS) {
        const bool is64 = (g_is64 != 0);
        const int nb = gridDim.x - GEMM_BLOCKS;
        const int bb = blockIdx.x - GEMM_BLOCKS;
        const int stride = nb * 256;
        for (int i = bb * 256 + tid; i < EE; i += stride) {
            int d = is64 ? ei[2 * (EE + i)] : ei[EE + i];
            g_rank[i] = atomicAdd(&g_cnt[d], 1);
        }
        for (int i = bb * 256 + tid; i < NN; i += stride) {
            int b = is64 ? bt[2 * i] : bt[i];
            g_batch[i] = b;
            atomicAdd(&g_gcnt[b], 1.f);
        }
        return;
    }

    const int warp = tid >> 5, lane = tid & 31;
    const int g = lane >> 2, tq = lane & 3;
    const int base = blockIdx.x * 128;

    for (int t = tid; t < DIN * HIDD; t += 256) {
        int k = t >> 6, n = t & 63;
        sB[n][k] = __float2half(W[t]);
    }

    float c[8][4];
#pragma unroll
    for (int nt = 0; nt < 8; nt++)
#pragma unroll
        for (int j = 0; j < 4; j++) c[nt][j] = 0.f;

#pragma unroll
    for (int half = 0; half < 2; half++) {
        __syncthreads();
        for (int t = tid; t < 128 * 32; t += 256) {
            int row = t >> 5, p = t & 31;
            int node = base + row;
            float2 v = (node < NN)
                ? *(const float2*)&x[(long)node * DIN + half * 64 + p * 2]
                : make_float2(0.f, 0.f);
            *(__half2*)&sA[row][p * 2] = __floats2half2_rn(v.x, v.y);
        }
        __syncthreads();
#pragma unroll
        for (int ks = 0; ks < 4; ks++) {
            int k0 = ks * 16 + tq * 2;
            unsigned a0 = *(const unsigned*)&sA[warp * 16 + g][k0];
            unsigned a1 = *(const unsigned*)&sA[warp * 16 + g + 8][k0];
            unsigned a2 = *(const unsigned*)&sA[warp * 16 + g][k0 + 8];
            unsigned a3 = *(const unsigned*)&sA[warp * 16 + g + 8][k0 + 8];
#pragma unroll
            for (int nt = 0; nt < 8; nt++) {
                unsigned b0 = *(const unsigned*)&sB[nt * 8 + g][half * 64 + k0];
                unsigned b1 = *(const unsigned*)&sB[nt * 8 + g][half * 64 + k0 + 8];
                hmma(c[nt], a0, a1, a2, a3, b0, b1);
            }
        }
    }

    const int r0 = base + warp * 16 + g;
    const int r1 = r0 + 8;
#pragma unroll
    for (int nt = 0; nt < 8; nt++) {
        int c0 = nt * 8 + tq * 2;
        float bv0 = bias[c0], bv1 = bias[c0 + 1];
        if (r0 < NN)
            *(__half2*)&C[(long)r0 * HIDD + c0] =
                __floats2half2_rn(c[nt][0] + bv0, c[nt][1] + bv1);
        if (r1 < NN)
            *(__half2*)&C[(long)r1 * HIDD + c0] =
                __floats2half2_rn(c[nt][2] + bv0, c[nt][3] + bv1);
    }
}

// ---------------- merged prefix scan (block scans + last-block top scan) -----
__global__ void k_scan() {
    __shared__ int s[256];
    __shared__ int p[256];
    __shared__ bool amLast;
    int b = blockIdx.x, t = threadIdx.x, i = b * 256 + t;
    int v = (i < NN) ? g_cnt[i] : 0;
    if (i < NN) g_dinv[i] = rsqrtf((float)(v + 1));
    s[t] = v; __syncthreads();
#pragma unroll
    for (int o = 1; o < 256; o <<= 1) {
        int x = (t >= o) ? s[t - o] : 0;
        __syncthreads();
        s[t] += x;
        __syncthreads();
    }
    if (i < NN) g_off[i] = s[t] - v;
    if (t == 255) g_bsum[b] = s[255];

    __threadfence();
    if (t == 0) amLast = (atomicAdd(&g_scan_ct, 1) == gridDim.x - 1);
    __syncthreads();
    if (!amLast) return;

    int e0 = (2 * t < NB_SCAN) ? g_bsum[2 * t] : 0;
    int e1 = (2 * t + 1 < NB_SCAN) ? g_bsum[2 * t + 1] : 0;
    int pv = e0 + e1;
    p[t] = pv; __syncthreads();
#pragma unroll
    for (int o = 1; o < 256; o <<= 1) {
        int x = (t >= o) ? p[t - o] : 0;
        __syncthreads();
        p[t] += x;
        __syncthreads();
    }
    int excl = p[t] - pv;
    g_boff[2 * t] = excl;
    g_boff[2 * t + 1] = excl + e0;
    if (2 * t == (NN >> 8)) g_off[NN] = EE - excl;
    if (2 * t + 1 == (NN >> 8)) g_off[NN] = EE - (excl + e0);
}

// ---------------- mega 2: [blocks 0..AUX-1] place (no atomic) | [rest] hw0 ---
__global__ void __launch_bounds__(256) k_mega_place(
        const int* __restrict__ ei, const __half* __restrict__ A,
        const float* __restrict__ W, unsigned char* __restrict__ C8) {
    __shared__ __half sB[64][72];
    const int tid = threadIdx.x;

    if (blockIdx.x < AUX_BLOCKS) {
        const bool is64 = (g_is64 != 0);
        const int stride = AUX_BLOCKS * 256;
        for (int e = blockIdx.x * 256 + tid; e < EE; e += stride) {
            int s = is64 ? ei[2 * e] : ei[e];
            int d = is64 ? ei[2 * (EE + e)] : ei[EE + e];
            float w = g_dinv[s] * g_dinv[d];
            int pos = g_off[d] + g_boff[d >> 8] + g_rank[e];
            g_csr[pos] = make_int2(s, __float_as_int(w));
        }
        return;
    }

    const int warp = tid >> 5, lane = tid & 31;
    const int g = lane >> 2, tq = lane & 3;

    for (int t = tid; t < HIDD * HIDD; t += 256) {
        int k = t >> 6, n = t & 63;
        sB[n][k] = __float2half(W[t]);
    }
    __syncthreads();

    const int r0 = (blockIdx.x - AUX_BLOCKS) * 128 + warp * 16 + g;
    const int r1 = r0 + 8;
    const bool v0 = (r0 < NN), v1 = (r1 < NN);
    const __half* A0 = A + (long)(v0 ? r0 : 0) * HIDD;
    const __half* A1 = A + (long)(v1 ? r1 : 0) * HIDD;

    float c[8][4];
#pragma unroll
    for (int nt = 0; nt < 8; nt++)
#pragma unroll
        for (int j = 0; j < 4; j++) c[nt][j] = 0.f;

#pragma unroll
    for (int ks = 0; ks < 4; ks++) {
        int k0 = ks * 16 + tq * 2;
        unsigned a0 = *(const unsigned*)&A0[k0];
        unsigned a1 = *(const unsigned*)&A1[k0];
        unsigned a2 = *(const unsigned*)&A0[k0 + 8];
        unsigned a3 = *(const unsigned*)&A1[k0 + 8];
#pragma unroll
        for (int nt = 0; nt < 8; nt++) {
            unsigned b0 = *(const unsigned*)&sB[nt * 8 + g][k0];
            unsigned b1 = *(const unsigned*)&sB[nt * 8 + g][k0 + 8];
            hmma(c[nt], a0, a1, a2, a3, b0, b1);
        }
    }

#pragma unroll
    for (int nt = 0; nt < 8; nt++) {
        int c0 = nt * 8 + tq * 2;
        if (v0) *(unsigned short*)&C8[(long)r0 * HIDD + c0] = f2_to_fp8x2(c[nt][0], c[nt][1]);
        if (v1) *(unsigned short*)&C8[(long)r1 * HIDD + c0] = f2_to_fp8x2(c[nt][2], c[nt][3]);
    }
}

// ---------------- standalone layer GEMM: hw8 = fp8(h @ W) --------------------
__global__ void __launch_bounds__(256) k_gemm_h_mma(
        const __half* __restrict__ A, const float* __restrict__ W,
        unsigned char* __restrict__ C8) {
    __shared__ __half sB[64][72];
    const int tid = threadIdx.x;
    const int warp = tid >> 5, lane = tid & 31;
    const int g = lane >> 2, tq = lane & 3;

    for (int t = tid; t < HIDD * HIDD; t += 256) {
        int k = t >> 6, n = t & 63;
        sB[n][k] = __float2half(W[t]);
    }
    __syncthreads();

    const int r0 = blockIdx.x * 128 + warp * 16 + g;
    const int r1 = r0 + 8;
    const bool v0 = (r0 < NN), v1 = (r1 < NN);
    const __half* A0 = A + (long)(v0 ? r0 : 0) * HIDD;
    const __half* A1 = A + (long)(v1 ? r1 : 0) * HIDD;

    float c[8][4];
#pragma unroll
    for (int nt = 0; nt < 8; nt++)
#pragma unroll
        for (int j = 0; j < 4; j++) c[nt][j] = 0.f;

#pragma unroll
    for (int ks = 0; ks < 4; ks++) {
        int k0 = ks * 16 + tq * 2;
        unsigned a0 = *(const unsigned*)&A0[k0];
        unsigned a1 = *(const unsigned*)&A1[k0];
        unsigned a2 = *(const unsigned*)&A0[k0 + 8];
        unsigned a3 = *(const unsigned*)&A1[k0 + 8];
#pragma unroll
        for (int nt = 0; nt < 8; nt++) {
            unsigned b0 = *(const unsigned*)&sB[nt * 8 + g][k0];
            unsigned b1 = *(const unsigned*)&sB[nt * 8 + g][k0 + 8];
            hmma(c[nt], a0, a1, a2, a3, b0, b1);
        }
    }

#pragma unroll
    for (int nt = 0; nt < 8; nt++) {
        int c0 = nt * 8 + tq * 2;
        if (v0) *(unsigned short*)&C8[(long)r0 * HIDD + c0] = f2_to_fp8x2(c[nt][0], c[nt][1]);
        if (v1) *(unsigned short*)&C8[(long)r1 * HIDD + c0] = f2_to_fp8x2(c[nt][2], c[nt][3]);
    }
}

// ---------------- gather + epilogue (R11 proven form) ------------------------
// warp-per-node, fp8 input, fp32 accumulation; POOL=1: pool into g_gsum.
template <int POOL>
__global__ void k_gather_ep(const unsigned char* __restrict__ hw8,
                            const float* __restrict__ cb,
                            const float* __restrict__ gamma,
                            const float* __restrict__ beta,
                            const float* __restrict__ mean,
                            const float* __restrict__ var,
                            __half* __restrict__ hout) {
    int gw = (blockIdx.x * blockDim.x + threadIdx.x) >> 5;
    int lane = threadIdx.x & 31;
    if (gw >= NN) return;
    const int c0 = lane * 2, c1 = c0 + 1;
    float di = g_dinv[gw];
    float swt = di * di;
    float2 self = fp8x2_to_f2(*(const unsigned short*)&hw8[(long)gw * HIDD + c0]);
    float2 acc = make_float2(self.x * swt, self.y * swt);
    int e = g_off[gw] + g_boff[gw >> 8];
    int end = g_off[gw + 1] + g_boff[(gw + 1) >> 8];
    for (; e + 1 < end; e += 2) {
        int2 m0 = g_csr[e];
        int2 m1 = g_csr[e + 1];
        float w0 = __int_as_float(m0.y), w1 = __int_as_float(m1.y);
        float2 v0 = fp8x2_to_f2(*(const unsigned short*)&hw8[(long)m0.x * HIDD + c0]);
        float2 v1 = fp8x2_to_f2(*(const unsigned short*)&hw8[(long)m1.x * HIDD + c0]);
        acc.x += w0 * v0.x + w1 * v1.x;
        acc.y += w0 * v0.y + w1 * v1.y;
    }
    if (e < end) {
        int2 m = g_csr[e];
        float w = __int_as_float(m.y);
        float2 v = fp8x2_to_f2(*(const unsigned short*)&hw8[(long)m.x * HIDD + c0]);
        acc.x += w * v.x;
        acc.y += w * v.y;
    }
    float sc0 = gamma[c0] * rsqrtf(var[c0] + BN_EPS);
    float sc1 = gamma[c1] * rsqrtf(var[c1] + BN_EPS);
    float sh0 = (cb[c0] - mean[c0]) * sc0 + beta[c0];
    float sh1 = (cb[c1] - mean[c1]) * sc1 + beta[c1];
    float o0 = fmaxf(acc.x * sc0 + sh0, 0.f);
    float o1 = fmaxf(acc.y * sc1 + sh1, 0.f);
    if (POOL) {
        int b = g_batch[gw];
        atomicAdd((float2*)&g_gsum[b * HIDD + c0], make_float2(o0, o1));
    } else {
        *(__half2*)&hout[(long)gw * HIDD + c0] = __floats2half2_rn(o0, o1);
    }
}

// ---------------- MLP head ----------------
__global__ void k_mlp(const float* __restrict__ W1, const float* __restrict__ b1,
                      const float* __restrict__ W2, const float* __restrict__ b2,
                      const float* __restrict__ W3, const float* __restrict__ b3,
                      float* __restrict__ out) {
    __shared__ float v[64], a1[64], a2[32];
    int g = blockIdx.x;
    int c = threadIdx.x;
    float cnt = fmaxf(g_gcnt[g], 1.f);
    v[c] = g_gsum[g * HIDD + c] / cnt;
    __syncthreads();
    float s = b1[c];
#pragma unroll
    for (int k = 0; k < 64; k++) s += v[k] * W1[k * 64 + c];
    a1[c] = fmaxf(s, 0.f);
    __syncthreads();
    if (c < 32) {
        float s2 = b2[c];
#pragma unroll
        for (int k = 0; k < 64; k++) s2 += a1[k] * W2[k * 32 + c];
        a2[c] = fmaxf(s2, 0.f);
    }
    __syncthreads();
    if (c < 32) {
        float p = a2[c] * W3[c];
#pragma unroll
        for (int o = 16; o > 0; o >>= 1) p += __shfl_down_sync(0xffffffff, p, o);
        if (c == 0) out[g] = p + b3[0];
    }
}

// ---------------- launch ----------------
extern "C" void kernel_launch(void* const* d_in, const int* in_sizes, int n_in,
                              void* d_out, int out_size) {
    const float* x      = (const float*)d_in[0];
    const int*   ei     = (const int*)d_in[1];
    const int*   bt     = (const int*)d_in[2];
    const float* W_in   = (const float*)d_in[3];
    const float* b_in   = (const float*)d_in[4];
    const float* conv_W = (const float*)d_in[5];
    const float* conv_b = (const float*)d_in[6];
    const float* gamma  = (const float*)d_in[7];
    const float* beta   = (const float*)d_in[8];
    const float* mean   = (const float*)d_in[9];
    const float* var    = (const float*)d_in[10];
    const float* W1     = (const float*)d_in[11];
    const float* b1     = (const float*)d_in[12];
    const float* W2     = (const float*)d_in[13];
    const float* b2     = (const float*)d_in[14];
    const float* W3     = (const float*)d_in[15];
    const float* b3     = (const float*)d_in[16];
    float* out = (float*)d_out;

    __half* p_h = nullptr;
    unsigned char* p_hw8 = nullptr;
    cudaGetSymbolAddress((void**)&p_h, g_h);
    cudaGetSymbolAddress((void**)&p_hw8, g_hw8);

    const int gather_blocks = (NN * 32 + 255) / 256;

    k_init<<<(NN + 255) / 256, 256>>>(ei);
    // overlap: input GEMM + edge counting (with rank capture)
    k_mega_in<<<GEMM_BLOCKS + AUX_BLOCKS, 256>>>(x, W_in, b_in, ei, bt, p_h);
    k_scan<<<NB_SCAN, 256>>>();
    // overlap: atomic-free CSR placement + layer-0 transform (fp8 out)
    k_mega_place<<<AUX_BLOCKS + GEMM_BLOCKS, 256>>>(ei, p_h, conv_W, p_hw8);

    // layer 0 gather -> h1
    k_gather_ep<0><<<gather_blocks, 256>>>(p_hw8, conv_b, gamma, beta, mean, var, p_h);
    // layer 1
    k_gemm_h_mma<<<GEMM_BLOCKS, 256>>>(p_h, conv_W + 1L * HIDD * HIDD, p_hw8);
    k_gather_ep<0><<<gather_blocks, 256>>>(p_hw8, conv_b + HIDD, gamma + HIDD,
                                           beta + HIDD, mean + HIDD, var + HIDD, p_h);
    // layer 2
    k_gemm_h_mma<<<GEMM_BLOCKS, 256>>>(p_h, conv_W + 2L * HIDD * HIDD, p_hw8);
    k_gather_ep<1><<<gather_blocks, 256>>>(p_hw8, conv_b + 2 * HIDD, gamma + 2 * HIDD,
                                           beta + 2 * HIDD, mean + 2 * HIDD,
                                           var + 2 * HIDD, p_h);

    k_mlp<<<GG, 64>>>(W1, b1, W2, b2, W3, b3, out);
}

// round 14
// speedup vs baseline: 1.3235x; 1.0823x over previous
#include <cuda_runtime.h>
#include <cuda_fp16.h>

#define NN 100000
#define EE 1600000
#define DIN 128
#define HIDD 64
#define GG 256
#define NLAYERS 3
#define BN_EPS 1e-5f
#define NB_SCAN ((NN + 255) / 256)   // 391
#define GEMM_BLOCKS 782              // ceil(NN/128)
#define AUX_BLOCKS 2048

// ---------------- device scratch (no allocs allowed) ----------------
__device__ __align__(16) int    g_cnt[NN];
__device__ __align__(16) int    g_fill[NN];
__device__ __align__(16) int    g_off[NN + 1];   // block-local exclusive prefix
__device__ __align__(16) int    g_bsum[NB_SCAN];
__device__ __align__(16) int    g_boff[512];     // per-256-block absolute base
__device__ __align__(16) float  g_dinv[NN];
__device__ __align__(16) int    g_csr[EE];       // src only (rows are pre-scaled)
__device__ __align__(16) int    g_batch[NN];
__device__ __align__(16) __half g_h[NN * HIDD];           // fp16 (GEMM A operand)
__device__ __align__(16) unsigned char g_hw8[NN * HIDD];  // fp8: dinv[row]*(h@W)
__device__ __align__(16) float  g_gsum[GG * HIDD];
__device__ __align__(16) float  g_gcnt[GG];
__device__ int g_is64;
__device__ int g_scan_ct;

// ---------------- fp8 helpers ----------------
__device__ __forceinline__ unsigned short f2_to_fp8x2(float lo, float hi) {
    unsigned short r;
    asm("cvt.rn.satfinite.e4m3x2.f32 %0, %2, %1;" : "=h"(r) : "f"(lo), "f"(hi));
    return r;   // byte0 = lo, byte1 = hi
}
__device__ __forceinline__ float2 fp8x2_to_f2(unsigned short v) {
    unsigned h2;
    asm("cvt.rn.f16x2.e4m3x2 %0, %1;" : "=r"(h2) : "h"(v));
    return __half22float2(*(__half2*)&h2);
}

// ---------------- init (+ inline dtype detection) ----------------
__global__ void k_init(const int* __restrict__ ei) {
    int i = blockIdx.x * blockDim.x + threadIdx.x;
    if (i < NN) { g_cnt[i] = 0; g_fill[i] = 0; }
    if (i < GG * HIDD) g_gsum[i] = 0.f;
    if (i < GG) g_gcnt[i] = 0.f;
    if (i == 0) {
        g_scan_ct = 0;
        int nz = 0;
        for (int j = 0; j < 32; j++) nz |= ei[2 * j + 1];
        g_is64 = (nz == 0) ? 1 : 0;
    }
}

// ---------------- HMMA m16n8k16 (fp16 x fp16 -> fp32) ----------------
__device__ __forceinline__ void hmma(float* c, unsigned a0, unsigned a1,
                                     unsigned a2, unsigned a3,
                                     unsigned b0, unsigned b1) {
    asm("mma.sync.aligned.m16n8k16.row.col.f32.f16.f16.f32 "
        "{%0,%1,%2,%3}, {%4,%5,%6,%7}, {%8,%9}, {%0,%1,%2,%3};"
        : "+f"(c[0]), "+f"(c[1]), "+f"(c[2]), "+f"(c[3])
        : "r"(a0), "r"(a1), "r"(a2), "r"(a3), "r"(b0), "r"(b1));
}

// ---------------- mega 1: [blocks 0..781] h0 GEMM | [rest] count -------------
__global__ void __launch_bounds__(256) k_mega_in(
        const float* __restrict__ x, const float* __restrict__ W,
        const float* __restrict__ bias, const int* __restrict__ ei,
        const int* __restrict__ bt, __half* __restrict__ C) {
    __shared__ __half sA[128][72];
    __shared__ __half sB[64][136];
    const int tid = threadIdx.x;

    if (blockIdx.x >= GEMM_BLOCKS) {
        const bool is64 = (g_is64 != 0);
        const int nb = gridDim.x - GEMM_BLOCKS;
        const int bb = blockIdx.x - GEMM_BLOCKS;
        const int stride = nb * 256;
        for (int i = bb * 256 + tid; i < EE; i += stride) {
            int d = is64 ? ei[2 * (EE + i)] : ei[EE + i];
            atomicAdd(&g_cnt[d], 1);
        }
        for (int i = bb * 256 + tid; i < NN; i += stride) {
            int b = is64 ? bt[2 * i] : bt[i];
            g_batch[i] = b;
            atomicAdd(&g_gcnt[b], 1.f);
        }
        return;
    }

    const int warp = tid >> 5, lane = tid & 31;
    const int g = lane >> 2, tq = lane & 3;
    const int base = blockIdx.x * 128;

    for (int t = tid; t < DIN * HIDD; t += 256) {
        int k = t >> 6, n = t & 63;
        sB[n][k] = __float2half(W[t]);
    }

    float c[8][4];
#pragma unroll
    for (int nt = 0; nt < 8; nt++)
#pragma unroll
        for (int j = 0; j < 4; j++) c[nt][j] = 0.f;

#pragma unroll
    for (int half = 0; half < 2; half++) {
        __syncthreads();
        for (int t = tid; t < 128 * 32; t += 256) {
            int row = t >> 5, p = t & 31;
            int node = base + row;
            float2 v = (node < NN)
                ? *(const float2*)&x[(long)node * DIN + half * 64 + p * 2]
                : make_float2(0.f, 0.f);
            *(__half2*)&sA[row][p * 2] = __floats2half2_rn(v.x, v.y);
        }
        __syncthreads();
#pragma unroll
        for (int ks = 0; ks < 4; ks++) {
            int k0 = ks * 16 + tq * 2;
            unsigned a0 = *(const unsigned*)&sA[warp * 16 + g][k0];
            unsigned a1 = *(const unsigned*)&sA[warp * 16 + g + 8][k0];
            unsigned a2 = *(const unsigned*)&sA[warp * 16 + g][k0 + 8];
            unsigned a3 = *(const unsigned*)&sA[warp * 16 + g + 8][k0 + 8];
#pragma unroll
            for (int nt = 0; nt < 8; nt++) {
                unsigned b0 = *(const unsigned*)&sB[nt * 8 + g][half * 64 + k0];
                unsigned b1 = *(const unsigned*)&sB[nt * 8 + g][half * 64 + k0 + 8];
                hmma(c[nt], a0, a1, a2, a3, b0, b1);
            }
        }
    }

    const int r0 = base + warp * 16 + g;
    const int r1 = r0 + 8;
#pragma unroll
    for (int nt = 0; nt < 8; nt++) {
        int c0 = nt * 8 + tq * 2;
        float bv0 = bias[c0], bv1 = bias[c0 + 1];
        if (r0 < NN)
            *(__half2*)&C[(long)r0 * HIDD + c0] =
                __floats2half2_rn(c[nt][0] + bv0, c[nt][1] + bv1);
        if (r1 < NN)
            *(__half2*)&C[(long)r1 * HIDD + c0] =
                __floats2half2_rn(c[nt][2] + bv0, c[nt][3] + bv1);
    }
}

// ---------------- merged prefix scan (block scans + last-block top scan) -----
__global__ void k_scan() {
    __shared__ int s[256];
    __shared__ int p[256];
    __shared__ bool amLast;
    int b = blockIdx.x, t = threadIdx.x, i = b * 256 + t;
    int v = (i < NN) ? g_cnt[i] : 0;
    if (i < NN) g_dinv[i] = rsqrtf((float)(v + 1));
    s[t] = v; __syncthreads();
#pragma unroll
    for (int o = 1; o < 256; o <<= 1) {
        int x = (t >= o) ? s[t - o] : 0;
        __syncthreads();
        s[t] += x;
        __syncthreads();
    }
    if (i < NN) g_off[i] = s[t] - v;
    if (t == 255) g_bsum[b] = s[255];

    __threadfence();
    if (t == 0) amLast = (atomicAdd(&g_scan_ct, 1) == gridDim.x - 1);
    __syncthreads();
    if (!amLast) return;

    int e0 = (2 * t < NB_SCAN) ? g_bsum[2 * t] : 0;
    int e1 = (2 * t + 1 < NB_SCAN) ? g_bsum[2 * t + 1] : 0;
    int pv = e0 + e1;
    p[t] = pv; __syncthreads();
#pragma unroll
    for (int o = 1; o < 256; o <<= 1) {
        int x = (t >= o) ? p[t - o] : 0;
        __syncthreads();
        p[t] += x;
        __syncthreads();
    }
    int excl = p[t] - pv;
    g_boff[2 * t] = excl;
    g_boff[2 * t + 1] = excl + e0;
    if (2 * t == (NN >> 8)) g_off[NN] = EE - excl;
    if (2 * t + 1 == (NN >> 8)) g_off[NN] = EE - (excl + e0);
}

// ---------------- mega 2: [blocks 0..AUX-1] place (src only) | [rest] hw0 ----
// GEMM epilogue scales by dinv[row] before fp8 quantization.
__global__ void __launch_bounds__(256) k_mega_place(
        const int* __restrict__ ei, const __half* __restrict__ A,
        const float* __restrict__ W, unsigned char* __restrict__ C8) {
    __shared__ __half sB[64][72];
    const int tid = threadIdx.x;

    if (blockIdx.x < AUX_BLOCKS) {
        const bool is64 = (g_is64 != 0);
        const int stride = AUX_BLOCKS * 256;
        for (int e = blockIdx.x * 256 + tid; e < EE; e += stride) {
            int s = is64 ? ei[2 * e] : ei[e];
            int d = is64 ? ei[2 * (EE + e)] : ei[EE + e];
            int pos = g_off[d] + g_boff[d >> 8] + atomicAdd(&g_fill[d], 1);
            g_csr[pos] = s;
        }
        return;
    }

    const int warp = tid >> 5, lane = tid & 31;
    const int g = lane >> 2, tq = lane & 3;

    for (int t = tid; t < HIDD * HIDD; t += 256) {
        int k = t >> 6, n = t & 63;
        sB[n][k] = __float2half(W[t]);
    }
    __syncthreads();

    const int r0 = (blockIdx.x - AUX_BLOCKS) * 128 + warp * 16 + g;
    const int r1 = r0 + 8;
    const bool v0 = (r0 < NN), v1 = (r1 < NN);
    const __half* A0 = A + (long)(v0 ? r0 : 0) * HIDD;
    const __half* A1 = A + (long)(v1 ? r1 : 0) * HIDD;

    float c[8][4];
#pragma unroll
    for (int nt = 0; nt < 8; nt++)
#pragma unroll
        for (int j = 0; j < 4; j++) c[nt][j] = 0.f;

#pragma unroll
    for (int ks = 0; ks < 4; ks++) {
        int k0 = ks * 16 + tq * 2;
        unsigned a0 = *(const unsigned*)&A0[k0];
        unsigned a1 = *(const unsigned*)&A1[k0];
        unsigned a2 = *(const unsigned*)&A0[k0 + 8];
        unsigned a3 = *(const unsigned*)&A1[k0 + 8];
#pragma unroll
        for (int nt = 0; nt < 8; nt++) {
            unsigned b0 = *(const unsigned*)&sB[nt * 8 + g][k0];
            unsigned b1 = *(const unsigned*)&sB[nt * 8 + g][k0 + 8];
            hmma(c[nt], a0, a1, a2, a3, b0, b1);
        }
    }

    const float d0 = v0 ? g_dinv[r0] : 0.f;
    const float d1 = v1 ? g_dinv[r1] : 0.f;
#pragma unroll
    for (int nt = 0; nt < 8; nt++) {
        int c0 = nt * 8 + tq * 2;
        if (v0) *(unsigned short*)&C8[(long)r0 * HIDD + c0] =
            f2_to_fp8x2(c[nt][0] * d0, c[nt][1] * d0);
        if (v1) *(unsigned short*)&C8[(long)r1 * HIDD + c0] =
            f2_to_fp8x2(c[nt][2] * d1, c[nt][3] * d1);
    }
}

// ---------------- standalone layer GEMM: hw8 = fp8(dinv[row] * (h @ W)) ------
__global__ void __launch_bounds__(256) k_gemm_h_mma(
        const __half* __restrict__ A, const float* __restrict__ W,
        unsigned char* __restrict__ C8) {
    __shared__ __half sB[64][72];
    const int tid = threadIdx.x;
    const int warp = tid >> 5, lane = tid & 31;
    const int g = lane >> 2, tq = lane & 3;

    for (int t = tid; t < HIDD * HIDD; t += 256) {
        int k = t >> 6, n = t & 63;
        sB[n][k] = __float2half(W[t]);
    }
    __syncthreads();

    const int r0 = blockIdx.x * 128 + warp * 16 + g;
    const int r1 = r0 + 8;
    const bool v0 = (r0 < NN), v1 = (r1 < NN);
    const __half* A0 = A + (long)(v0 ? r0 : 0) * HIDD;
    const __half* A1 = A + (long)(v1 ? r1 : 0) * HIDD;

    float c[8][4];
#pragma unroll
    for (int nt = 0; nt < 8; nt++)
#pragma unroll
        for (int j = 0; j < 4; j++) c[nt][j] = 0.f;

#pragma unroll
    for (int ks = 0; ks < 4; ks++) {
        int k0 = ks * 16 + tq * 2;
        unsigned a0 = *(const unsigned*)&A0[k0];
        unsigned a1 = *(const unsigned*)&A1[k0];
        unsigned a2 = *(const unsigned*)&A0[k0 + 8];
        unsigned a3 = *(const unsigned*)&A1[k0 + 8];
#pragma unroll
        for (int nt = 0; nt < 8; nt++) {
            unsigned b0 = *(const unsigned*)&sB[nt * 8 + g][k0];
            unsigned b1 = *(const unsigned*)&sB[nt * 8 + g][k0 + 8];
            hmma(c[nt], a0, a1, a2, a3, b0, b1);
        }
    }

    const float d0 = v0 ? g_dinv[r0] : 0.f;
    const float d1 = v1 ? g_dinv[r1] : 0.f;
#pragma unroll
    for (int nt = 0; nt < 8; nt++) {
        int c0 = nt * 8 + tq * 2;
        if (v0) *(unsigned short*)&C8[(long)r0 * HIDD + c0] =
            f2_to_fp8x2(c[nt][0] * d0, c[nt][1] * d0);
        if (v1) *(unsigned short*)&C8[(long)r1 * HIDD + c0] =
            f2_to_fp8x2(c[nt][2] * d1, c[nt][3] * d1);
    }
}

// ---------------- gather + epilogue: h = relu(BN(dinv_d * Σ hs + cb)) --------
// warp-per-node, R11 lane layout (lane = cols 2L, 2L+1), weight-free sum,
// unroll x4 (4 independent row-load chains). POOL=1: pool into g_gsum.
template <int POOL>
__global__ void k_gather_ep(const unsigned char* __restrict__ hw8,
                            const float* __restrict__ cb,
                            const float* __restrict__ gamma,
                            const float* __restrict__ beta,
                            const float* __restrict__ mean,
                            const float* __restrict__ var,
                            __half* __restrict__ hout) {
    int gw = (blockIdx.x * blockDim.x + threadIdx.x) >> 5;
    int lane = threadIdx.x & 31;
    if (gw >= NN) return;
    const int c0 = lane * 2, c1 = c0 + 1;
    const float di = g_dinv[gw];
    // self term: hs[d] (already dinv[d]-scaled)
    float2 acc = fp8x2_to_f2(*(const unsigned short*)&hw8[(long)gw * HIDD + c0]);
    int e = g_off[gw] + g_boff[gw >> 8];
    const int end = g_off[gw + 1] + g_boff[(gw + 1) >> 8];
    for (; e + 3 < end; e += 4) {
        int s0 = g_csr[e];
        int s1 = g_csr[e + 1];
        int s2 = g_csr[e + 2];
        int s3 = g_csr[e + 3];
        float2 v0 = fp8x2_to_f2(*(const unsigned short*)&hw8[(long)s0 * HIDD + c0]);
        float2 v1 = fp8x2_to_f2(*(const unsigned short*)&hw8[(long)s1 * HIDD + c0]);
        float2 v2 = fp8x2_to_f2(*(const unsigned short*)&hw8[(long)s2 * HIDD + c0]);
        float2 v3 = fp8x2_to_f2(*(const unsigned short*)&hw8[(long)s3 * HIDD + c0]);
        acc.x += (v0.x + v1.x) + (v2.x + v3.x);
        acc.y += (v0.y + v1.y) + (v2.y + v3.y);
    }
    for (; e < end; e++) {
        int s = g_csr[e];
        float2 v = fp8x2_to_f2(*(const unsigned short*)&hw8[(long)s * HIDD + c0]);
        acc.x += v.x;
        acc.y += v.y;
    }
    // epilogue: out = (di*acc)*sc + sh
    float sc0 = gamma[c0] * rsqrtf(var[c0] + BN_EPS);
    float sc1 = gamma[c1] * rsqrtf(var[c1] + BN_EPS);
    float sh0 = (cb[c0] - mean[c0]) * sc0 + beta[c0];
    float sh1 = (cb[c1] - mean[c1]) * sc1 + beta[c1];
    float o0 = fmaxf(acc.x * di * sc0 + sh0, 0.f);
    float o1 = fmaxf(acc.y * di * sc1 + sh1, 0.f);
    if (POOL) {
        int b = g_batch[gw];
        atomicAdd((float2*)&g_gsum[b * HIDD + c0], make_float2(o0, o1));
    } else {
        *(__half2*)&hout[(long)gw * HIDD + c0] = __floats2half2_rn(o0, o1);
    }
}

// ---------------- MLP head ----------------
__global__ void k_mlp(const float* __restrict__ W1, const float* __restrict__ b1,
                      const float* __restrict__ W2, const float* __restrict__ b2,
                      const float* __restrict__ W3, const float* __restrict__ b3,
                      float* __restrict__ out) {
    __shared__ float v[64], a1[64], a2[32];
    int g = blockIdx.x;
    int c = threadIdx.x;
    float cnt = fmaxf(g_gcnt[g], 1.f);
    v[c] = g_gsum[g * HIDD + c] / cnt;
    __syncthreads();
    float s = b1[c];
#pragma unroll
    for (int k = 0; k < 64; k++) s += v[k] * W1[k * 64 + c];
    a1[c] = fmaxf(s, 0.f);
    __syncthreads();
    if (c < 32) {
        float s2 = b2[c];
#pragma unroll
        for (int k = 0; k < 64; k++) s2 += a1[k] * W2[k * 32 + c];
        a2[c] = fmaxf(s2, 0.f);
    }
    __syncthreads();
    if (c < 32) {
        float p = a2[c] * W3[c];
#pragma unroll
        for (int o = 16; o > 0; o >>= 1) p += __shfl_down_sync(0xffffffff, p, o);
        if (c == 0) out[g] = p + b3[0];
    }
}

// ---------------- launch ----------------
extern "C" void kernel_launch(void* const* d_in, const int* in_sizes, int n_in,
                              void* d_out, int out_size) {
    const float* x      = (const float*)d_in[0];
    const int*   ei     = (const int*)d_in[1];
    const int*   bt     = (const int*)d_in[2];
    const float* W_in   = (const float*)d_in[3];
    const float* b_in   = (const float*)d_in[4];
    const float* conv_W = (const float*)d_in[5];
    const float* conv_b = (const float*)d_in[6];
    const float* gamma  = (const float*)d_in[7];
    const float* beta   = (const float*)d_in[8];
    const float* mean   = (const float*)d_in[9];
    const float* var    = (const float*)d_in[10];
    const float* W1     = (const float*)d_in[11];
    const float* b1     = (const float*)d_in[12];
    const float* W2     = (const float*)d_in[13];
    const float* b2     = (const float*)d_in[14];
    const float* W3     = (const float*)d_in[15];
    const float* b3     = (const float*)d_in[16];
    float* out = (float*)d_out;

    __half* p_h = nullptr;
    unsigned char* p_hw8 = nullptr;
    cudaGetSymbolAddress((void**)&p_h, g_h);
    cudaGetSymbolAddress((void**)&p_hw8, g_hw8);

    const int gather_blocks = (NN * 32 + 255) / 256;

    k_init<<<(NN + 255) / 256, 256>>>(ei);
    // overlap: input GEMM + edge counting
    k_mega_in<<<GEMM_BLOCKS + AUX_BLOCKS, 256>>>(x, W_in, b_in, ei, bt, p_h);
    k_scan<<<NB_SCAN, 256>>>();
    // overlap: src-only CSR placement + layer-0 transform (dinv-scaled fp8)
    k_mega_place<<<AUX_BLOCKS + GEMM_BLOCKS, 256>>>(ei, p_h, conv_W, p_hw8);

    // layer 0 gather -> h1
    k_gather_ep<0><<<gather_blocks, 256>>>(p_hw8, conv_b, gamma, beta, mean, var, p_h);
    // layer 1
    k_gemm_h_mma<<<GEMM_BLOCKS, 256>>>(p_h, conv_W + 1L * HIDD * HIDD, p_hw8);
    k_gather_ep<0><<<gather_blocks, 256>>>(p_hw8, conv_b + HIDD, gamma + HIDD,
                                           beta + HIDD, mean + HIDD, var + HIDD, p_h);
    // layer 2
    k_gemm_h_mma<<<GEMM_BLOCKS, 256>>>(p_h, conv_W + 2L * HIDD * HIDD, p_hw8);
    k_gather_ep<1><<<gather_blocks, 256>>>(p_hw8, conv_b + 2 * HIDD, gamma + 2 * HIDD,
                                           beta + 2 * HIDD, mean + 2 * HIDD,
                                           var + 2 * HIDD, p_h);

    k_mlp<<<GG, 64>>>(W1, b1, W2, b2, W3, b3, out);
}